// round 2
// baseline (speedup 1.0000x reference)
#include <cuda_runtime.h>
#include <cstdint>

// USR_EMB: out[row] = emb[searchsorted(userlist, x[row])], row-size 64 floats.
// NOTE: jax x64 is disabled in the dataset pipeline -> x and userlist are int32.
// HBM-write-bound: 210MB out + ~26MB emb-miss reads. Target ~35-50us.
//
// Layout: 16 threads per row, each copies one float4 (16B). Warp = 2 rows,
// fully coalesced 256B store segments. Index via verified fast path
// (userlist[u+1]==u for the arange-structured list) with binary-search
// fallback for full generality.

static constexpr int EMB = 64;
static constexpr int CHUNKS_PER_ROW = EMB / 4;  // 16 float4 per row

__global__ void __launch_bounds__(256) usr_emb_kernel(
    const int* __restrict__ x,
    const int* __restrict__ userlist,
    const float4* __restrict__ emb,      // [emb_rows][16] float4
    float4* __restrict__ out,            // [n_rows][16] float4
    int n_rows, int n_userlist, int emb_rows)
{
    int gtid = blockIdx.x * blockDim.x + threadIdx.x;
    int row   = gtid >> 4;       // 16 threads per row
    int chunk = gtid & 15;
    if (row >= n_rows) return;

    // All 16 lanes of a half-row read the same address -> single L1 request.
    int u = __ldg(&x[row]);

    // Fast path: for userlist = [-1, 0, 1, ..., N-1], searchsorted(u) = u+1.
    // Verify against the actual data; fall back to lower_bound if wrong.
    int idx = u + 1;
    bool ok = (idx >= 1) && (idx < n_userlist)
              && (__ldg(&userlist[idx]) == u)
              && (__ldg(&userlist[idx - 1]) < u);
    if (!ok) {
        // lower_bound: first i with userlist[i] >= u
        int lo = 0, hi = n_userlist;
        while (lo < hi) {
            int mid = (lo + hi) >> 1;
            if (__ldg(&userlist[mid]) < u) lo = mid + 1; else hi = mid;
        }
        idx = lo;
    }
    // Clamp like jax's gather (searchsorted can return n_userlist).
    if (idx >= emb_rows) idx = emb_rows - 1;
    if (idx < 0) idx = 0;

    // Gather one float4; emb table (25.6MB) is L2-resident -> mostly L2 hits.
    out[(size_t)row * CHUNKS_PER_ROW + chunk] =
        __ldg(&emb[(size_t)idx * CHUNKS_PER_ROW + chunk]);
}

extern "C" void kernel_launch(void* const* d_in, const int* in_sizes, int n_in,
                              void* d_out, int out_size)
{
    const int*   x        = (const int*)d_in[0];    // [B*H] int32
    const int*   userlist = (const int*)d_in[1];    // [N+1] int32
    const float* emb      = (const float*)d_in[2];  // [(N+1)*64] f32

    int n_rows     = in_sizes[0];          // 4096*200 = 819200
    int n_userlist = in_sizes[1];          // 100001
    int emb_rows   = in_sizes[2] / EMB;    // 100001

    long long total_threads = (long long)n_rows * CHUNKS_PER_ROW;
    int block = 256;
    int grid  = (int)((total_threads + block - 1) / block);

    usr_emb_kernel<<<grid, block>>>(x, userlist, (const float4*)emb,
                                    (float4*)d_out, n_rows, n_userlist, emb_rows);
}

// round 3
// speedup vs baseline: 1.6688x; 1.6688x over previous
#include <cuda_runtime.h>
#include <cstdint>

// USR_EMB: out[row] = emb[searchsorted(userlist, x[row])], 64 f32 per row.
// R2 post-mortem: latency-bound (all pipes ~35%). Fix: 4 rows per thread ->
// 4 independent memory chains per thread (MLP=4 at each stage), plus
// streaming cache hints so the 210MB write stream doesn't evict the
// L2-resident emb table (25.6MB) / userlist (0.4MB).

static constexpr int EMB = 64;
static constexpr int CPR = EMB / 4;   // 16 float4 chunks per row
static constexpr int R   = 4;         // rows per thread

__global__ void __launch_bounds__(256) usr_emb_kernel(
    const int* __restrict__ x,
    const int* __restrict__ userlist,
    const float4* __restrict__ emb,      // [emb_rows][16] float4
    float4* __restrict__ out,            // [n_rows][16] float4
    int n_rows, int n_userlist, int emb_rows)
{
    int gtid  = blockIdx.x * blockDim.x + threadIdx.x;
    int grp   = gtid >> 4;               // 16 lanes per row-group
    int chunk = gtid & 15;
    int row0  = grp * R;
    if (row0 >= n_rows) return;

    // Stage 1: batch the 4 index loads (independent; streaming, read-once).
    int u[R];
#pragma unroll
    for (int k = 0; k < R; k++) {
        int r = row0 + k;
        u[k] = (r < n_rows) ? __ldcs(&x[r]) : 0;
    }

    // Stage 2: verified fast path (userlist = [-1,0..N-1] => idx = u+1),
    // probes are independent across the 4 rows; binary-search fallback
    // keeps full generality.
    int idx[R];
#pragma unroll
    for (int k = 0; k < R; k++) {
        int i = u[k] + 1;
        bool ok = (i >= 1) && (i < n_userlist)
                  && (__ldg(&userlist[i]) == u[k])
                  && (__ldg(&userlist[i - 1]) < u[k]);
        if (!ok) {
            int lo = 0, hi = n_userlist;
            while (lo < hi) {
                int mid = (lo + hi) >> 1;
                if (__ldg(&userlist[mid]) < u[k]) lo = mid + 1; else hi = mid;
            }
            i = lo;
        }
        if (i >= emb_rows) i = emb_rows - 1;
        if (i < 0) i = 0;
        idx[k] = i;
    }

    // Stage 3: 4 independent gathers (L2-resident table -> L2 hits).
    float4 v[R];
#pragma unroll
    for (int k = 0; k < R; k++)
        v[k] = __ldg(&emb[(size_t)idx[k] * CPR + chunk]);

    // Stage 4: coalesced streaming stores (evict-first; never re-read).
#pragma unroll
    for (int k = 0; k < R; k++) {
        int r = row0 + k;
        if (r < n_rows)
            __stcs(&out[(size_t)r * CPR + chunk], v[k]);
    }
}

extern "C" void kernel_launch(void* const* d_in, const int* in_sizes, int n_in,
                              void* d_out, int out_size)
{
    const int*   x        = (const int*)d_in[0];    // [B*H] int32
    const int*   userlist = (const int*)d_in[1];    // [N+1] int32
    const float* emb      = (const float*)d_in[2];  // [(N+1)*64] f32

    int n_rows     = in_sizes[0];          // 819200
    int n_userlist = in_sizes[1];          // 100001
    int emb_rows   = in_sizes[2] / EMB;    // 100001

    int n_groups = (n_rows + R - 1) / R;
    long long total_threads = (long long)n_groups * CPR;
    int block = 256;
    int grid  = (int)((total_threads + block - 1) / block);

    usr_emb_kernel<<<grid, block>>>(x, userlist, (const float4*)emb,
                                    (float4*)d_out, n_rows, n_userlist, emb_rows);
}

// round 4
// speedup vs baseline: 1.8939x; 1.1349x over previous
#include <cuda_runtime.h>
#include <cstdint>

// USR_EMB: out[row] = emb[searchsorted(userlist, x[row])], 64 f32/row.
// R3 post-mortem: L1tex-issue-heavy — 16 lanes redundantly recompute each
// row's index (20 mem instrs per 8 rows vs 8 irreducible). R4: warp-
// cooperative indexing (lanes 0-15 compute 16 indices, shfl-broadcast),
// 8 rows/thread in 2 pipelined batches of 4 (MLP>=4), streaming hints keep
// the 25.6MB emb table L2-resident under the 210MB write stream.

static constexpr int EMB = 64;
static constexpr int CPR = EMB / 4;  // 16 float4 chunks per row
static constexpr int RPW = 16;       // rows per warp

__global__ void __launch_bounds__(256) usr_emb_kernel(
    const int* __restrict__ x,
    const int* __restrict__ userlist,
    const float4* __restrict__ emb,      // [emb_rows][16] float4
    float4* __restrict__ out,            // [n_rows][16] float4
    int n_rows, int n_userlist, int emb_rows)
{
    int warpId = (blockIdx.x * blockDim.x + threadIdx.x) >> 5;
    int lane   = threadIdx.x & 31;
    int group  = lane >> 4;              // 0 or 1: which 8-row half
    int chunk  = lane & 15;              // float4 within row
    int wrow0  = warpId * RPW;
    if (wrow0 >= n_rows) return;

    // ---- Cooperative index computation: lanes 0-15, one row each ----
    int myIdx = 0;
    if (lane < RPW) {
        int r = wrow0 + lane;
        int u = (r < n_rows) ? __ldcs(&x[r]) : 0;   // coalesced 64B, read-once
        // Fast path: userlist = [-1, 0..N-1] => searchsorted(u) = u+1.
        // Verified against data; binary-search fallback for generality.
        int i = u + 1;
        bool ok = (i >= 1) && (i < n_userlist)
                  && (__ldg(&userlist[i]) == u)
                  && (__ldg(&userlist[i - 1]) < u);
        if (!ok) {
            int lo = 0, hi = n_userlist;
            while (lo < hi) {
                int mid = (lo + hi) >> 1;
                if (__ldg(&userlist[mid]) < u) lo = mid + 1; else hi = mid;
            }
            i = lo;
        }
        if (i >= emb_rows) i = emb_rows - 1;
        if (i < 0) i = 0;
        myIdx = i;
    }
    __syncwarp();

    // Each thread fetches its 8 row-indices from the computing lanes.
    int idx[8];
#pragma unroll
    for (int k = 0; k < 8; k++)
        idx[k] = __shfl_sync(0xffffffffu, myIdx, group * 8 + k);

    int rowBase = wrow0 + group * 8;

    // ---- Two pipelined batches: 4 independent gathers, then 4 stores ----
#pragma unroll
    for (int b = 0; b < 2; b++) {
        float4 v[4];
#pragma unroll
        for (int k = 0; k < 4; k++)
            v[k] = __ldg(&emb[(size_t)idx[b * 4 + k] * CPR + chunk]);
#pragma unroll
        for (int k = 0; k < 4; k++) {
            int r = rowBase + b * 4 + k;
            if (r < n_rows)
                __stcs(&out[(size_t)r * CPR + chunk], v[k]);
        }
    }
}

extern "C" void kernel_launch(void* const* d_in, const int* in_sizes, int n_in,
                              void* d_out, int out_size)
{
    const int*   x        = (const int*)d_in[0];    // [B*H] int32
    const int*   userlist = (const int*)d_in[1];    // [N+1] int32
    const float* emb      = (const float*)d_in[2];  // [(N+1)*64] f32

    int n_rows     = in_sizes[0];          // 819200
    int n_userlist = in_sizes[1];          // 100001
    int emb_rows   = in_sizes[2] / EMB;    // 100001

    int n_warps = (n_rows + RPW - 1) / RPW;          // 51200
    long long total_threads = (long long)n_warps * 32;
    int block = 256;
    int grid  = (int)((total_threads + block - 1) / block);  // 6400

    usr_emb_kernel<<<grid, block>>>(x, userlist, (const float4*)emb,
                                    (float4*)d_out, n_rows, n_userlist, emb_rows);
}